// round 16
// baseline (speedup 1.0000x reference)
#include <cuda_runtime.h>

// ---------------- f32x2 packed-FMA helpers ----------------
typedef unsigned long long u64t;
__device__ __forceinline__ u64t pk2(float v){ u64t r; asm("mov.b64 %0,{%1,%1};" : "=l"(r) : "f"(v)); return r; }
__device__ __forceinline__ void fma2(u64t& d, u64t a, u64t b){ asm("fma.rn.f32x2 %0,%1,%2,%0;" : "+l"(d) : "l"(a), "l"(b)); }
__device__ __forceinline__ float2 up2(u64t v){ float2 f; asm("mov.b64 {%0,%1},%2;" : "=f"(f.x), "=f"(f.y) : "l"(v)); return f; }

// cp.async 4B with zero-fill when sz==0
__device__ __forceinline__ void cpa4(unsigned dst, const void* src, int sz){
    asm volatile("cp.async.ca.shared.global [%0], [%1], 4, %2;" :: "r"(dst), "l"(src), "r"(sz));
}
// cp.async 16B (L2-bypass-L1 .cg form)
__device__ __forceinline__ void cpa16(unsigned dst, const void* src){
    asm volatile("cp.async.cg.shared.global [%0], [%1], 16;" :: "r"(dst), "l"(src));
}

// ---------------- scratch (device globals; no allocation allowed) ----------------
__device__ float g_F1[2][64u*512u*512u];   // conv1 out, both nets (134 MB)
__device__ float g_F2[2][32u*256u*256u];   // conv2 out
__device__ float g_F3[2][16u*128u*128u];   // conv3 out
__device__ float g_POOL[2][4096];          // pooled features (c*256+p)
__device__ float g_MAT[2][4096];           // sMat (net0), cMat (net1), row-major 64x64
__device__ float g_CC[64*16384];           // compress output
__device__ float g_MEAN[64];               // row means of CC
__device__ float g_TFG[64*8192];           // T @ ccf[:, fgc]
__device__ float g_TF[64*16384];           // ccf with fg columns replaced
__device__ float g_CWT[512*64];            // compress weights transposed [c][o]

// ---------------- side stream for DAG-branch overlap (created pre-checkpoint) ----
static cudaStream_t g_s2 = nullptr;
static cudaEvent_t  g_evA = nullptr, g_evB = nullptr;
struct StreamInit {
    StreamInit() {
        cudaStreamCreateWithFlags(&g_s2, cudaStreamNonBlocking);
        cudaEventCreateWithFlags(&g_evA, cudaEventDisableTiming);
        cudaEventCreateWithFlags(&g_evB, cudaEventDisableTiming);
    }
};
static StreamInit g_streaminit;

// =====================================================================
// conv1: (3,1024,1024) -> (64,512,512), k=3 s=2 p=1, +bias, ReLU (scalar, proven)
// =====================================================================
__global__ void k_conv1(const float* __restrict__ img0, const float* __restrict__ img1,
                        const float* __restrict__ w0, const float* __restrict__ b0,
                        const float* __restrict__ w1, const float* __restrict__ b1)
{
    const int net = blockIdx.z;
    const float* __restrict__ img = net ? img1 : img0;
    const float* __restrict__ W   = net ? w1 : w0;
    const float* __restrict__ B   = net ? b1 : b0;

    __shared__ __align__(16) float s_w[64 * 28];
    __shared__ __align__(16) float s_in[3 * 33 * 65];
    __shared__ float s_b[64];

    const int tid = threadIdx.y * 16 + threadIdx.x;
    for (int i = tid; i < 64 * 28; i += 256) {
        int oc = i / 28, k = i - oc * 28;
        s_w[i] = (k < 27) ? W[oc * 27 + k] : 0.f;
    }
    if (tid < 64) s_b[tid] = B[tid];

    const int bx = blockIdx.x, by = blockIdx.y;
    const int ix0 = 2 * (bx * 32) - 1;
    const int iy0 = 2 * (by * 16) - 1;
    for (int i = tid; i < 3 * 33 * 65; i += 256) {
        int c = i / (33 * 65);
        int rem = i % (33 * 65);
        int r = rem / 65, col = rem % 65;
        int iy = iy0 + r, ix = ix0 + col;
        float v = 0.f;
        if (iy >= 0 && iy < 1024 && ix >= 0 && ix < 1024)
            v = img[(c * 1024 + iy) * 1024 + ix];
        s_in[i] = v;
    }
    __syncthreads();

    const int tx = threadIdx.x, ty = threadIdx.y;
    float r[54];
    #pragma unroll
    for (int c = 0; c < 3; c++)
        #pragma unroll
        for (int ky = 0; ky < 3; ky++) {
            int base = c * 33 * 65 + (2 * ty + ky) * 65 + 2 * tx;
            #pragma unroll
            for (int kx = 0; kx < 3; kx++) {
                r[(c * 3 + ky) * 6 + kx]     = s_in[base + kx];
                r[(c * 3 + ky) * 6 + 3 + kx] = s_in[base + 32 + kx];
            }
        }

    const int oy = by * 16 + ty;
    const int ox = bx * 32 + tx;
    float* outp = &g_F1[net][0] + (size_t)oy * 512 + ox;
    #pragma unroll 2
    for (int oc = 0; oc < 64; oc++) {
        float w[28];
        const float4* wr = (const float4*)&s_w[oc * 28];
        #pragma unroll
        for (int j = 0; j < 7; j++) {
            float4 t4 = wr[j];
            w[4*j] = t4.x; w[4*j+1] = t4.y; w[4*j+2] = t4.z; w[4*j+3] = t4.w;
        }
        float a0 = s_b[oc], a1 = s_b[oc];
        #pragma unroll
        for (int k = 0; k < 27; k++) {
            a0 += w[k] * r[(k / 3) * 6 + (k % 3)];
            a1 += w[k] * r[(k / 3) * 6 + 3 + (k % 3)];
        }
        outp[(size_t)oc * 262144]      = fmaxf(a0, 0.f);
        outp[(size_t)oc * 262144 + 16] = fmaxf(a1, 0.f);
    }
}

// =====================================================================
// conv2: f32x2 + 4-stage cp.async pipeline (proven, 135us)
// =====================================================================
__global__ void __launch_bounds__(256, 2) k_conv2(
        const float* __restrict__ w0, const float* __restrict__ b0,
        const float* __restrict__ w1, const float* __restrict__ b1)
{
    const int net = blockIdx.z;
    const float* __restrict__ W = net ? w1 : w0;   // (32,64,3,3)
    const float* __restrict__ B = net ? b1 : b0;
    const float* __restrict__ in = &g_F1[net][0];

    __shared__ __align__(16) float s_in[4][33 * 65];   // 4 x 2145
    __shared__ __align__(16) float s_w[4][9 * 32];     // 4 x 288, [t][oc]
    __shared__ float s_b[32];

    const int tid = threadIdx.x;
    if (tid < 32) s_b[tid] = B[tid];

    const int x0 = blockIdx.x * 32;
    const int y0 = blockIdx.y * 16;
    const int ix0 = 2 * x0 - 1;
    const int iy0 = 2 * y0 - 1;
    const int tx = tid & 15, og = (tid >> 4) & 3, ty = tid >> 6;

    int goff[9];
    #pragma unroll
    for (int j = 0; j < 9; j++) {
        int i = tid + j * 256;
        int rr = i / 65, col = i - rr * 65;
        int iy = iy0 + rr, ix = ix0 + col;
        bool ok = (i < 2145) && iy >= 0 && iy < 512 && ix >= 0 && ix < 512;
        goff[j] = ok ? (((iy * 512 + ix) << 2) | 1) : 0;
    }
    const int t0w = tid >> 5, oc0w = tid & 31;
    const int woff0 = (oc0w * 576 + t0w) << 2;
    const bool w1v = tid < 32;
    const int woff1 = (oc0w * 576 + 8) << 2;

    u64t acc2[4][8];
    #pragma unroll
    for (int j = 0; j < 4; j++)
        #pragma unroll
        for (int p = 0; p < 8; p++) acc2[j][p] = 0ull;

    auto issue = [&](int ic, int buf) {
        unsigned dw = (unsigned)__cvta_generic_to_shared(&s_w[buf][0]);
        const char* wB = (const char*)W + ic * 36;
        cpa4(dw + 4u * tid, wB + woff0, 4);
        if (w1v) cpa4(dw + 4u * (tid + 256), wB + woff1, 4);
        unsigned di = (unsigned)__cvta_generic_to_shared(&s_in[buf][0]);
        const char* iB = (const char*)in + (size_t)ic * 1048576u;
        #pragma unroll
        for (int j = 0; j < 8; j++) {
            int e = goff[j];
            cpa4(di + 4u * (tid + j * 256), iB + (e & ~3), (e & 1) << 2);
        }
        if (tid < 97) {
            int e = goff[8];
            cpa4(di + 4u * (tid + 2048), iB + (e & ~3), (e & 1) << 2);
        }
    };

    issue(0, 0); asm volatile("cp.async.commit_group;" ::: "memory");
    issue(1, 1); asm volatile("cp.async.commit_group;" ::: "memory");
    issue(2, 2); asm volatile("cp.async.commit_group;" ::: "memory");

    for (int k = 0; k < 64; k++) {
        asm volatile("cp.async.wait_group 2;" ::: "memory");
        __syncthreads();
        if (k + 3 < 64) issue(k + 3, (k + 3) & 3);
        asm volatile("cp.async.commit_group;" ::: "memory");

        const float* sp = s_in[k & 3];
        const float* sw = s_w[k & 3];
        #pragma unroll
        for (int t = 0; t < 9; t++) {
            const int ky = t / 3, kx = t - ky * 3;
            const u64t* wp = (const u64t*)&sw[t * 32 + og * 8];
            u64t w2[4];
            #pragma unroll
            for (int j = 0; j < 4; j++) w2[j] = wp[j];
            u64t b2[8];
            #pragma unroll
            for (int kk = 0; kk < 4; kk++) {
                int row = 2 * (ty + 4 * kk) + ky;
                b2[kk*2]   = pk2(sp[row * 65 + 2 * tx + kx]);
                b2[kk*2+1] = pk2(sp[row * 65 + 2 * tx + 32 + kx]);
            }
            #pragma unroll
            for (int j = 0; j < 4; j++)
                #pragma unroll
                for (int p = 0; p < 8; p++)
                    fma2(acc2[j][p], w2[j], b2[p]);
        }
    }

    float* outb = &g_F2[net][0];
    #pragma unroll
    for (int j = 0; j < 4; j++) {
        int oc0 = og * 8 + 2 * j;
        float bb0 = s_b[oc0], bb1 = s_b[oc0 + 1];
        #pragma unroll
        for (int k = 0; k < 4; k++) {
            int oy = y0 + ty + 4 * k;
            float2 vA = up2(acc2[j][k*2]);
            float2 vB = up2(acc2[j][k*2+1]);
            float* opA = &outb[((size_t)oc0 * 256 + oy) * 256 + x0 + tx];
            float* opB = &outb[((size_t)(oc0+1) * 256 + oy) * 256 + x0 + tx];
            opA[0]  = fmaxf(vA.x + bb0, 0.f);
            opB[0]  = fmaxf(vA.y + bb1, 0.f);
            opA[16] = fmaxf(vB.x + bb0, 0.f);
            opB[16] = fmaxf(vB.y + bb1, 0.f);
        }
    }
}

// =====================================================================
// conv3: (32,256,256) -> (16,128,128), +bias, NO relu (scalar, proven)
// =====================================================================
__global__ void k_conv3(const float* __restrict__ w0, const float* __restrict__ b0,
                        const float* __restrict__ w1, const float* __restrict__ b1)
{
    const int net = blockIdx.z;
    const float* __restrict__ W = net ? w1 : w0;   // (16,32,3,3)
    const float* __restrict__ B = net ? b1 : b0;
    const float* __restrict__ in = &g_F2[net][0];

    __shared__ __align__(16) float s_in[8 * 33 * 34];
    __shared__ __align__(16) float s_w[16 * 8 * 9];
    __shared__ float s_b[16];

    const int tid = threadIdx.x;
    if (tid < 16) s_b[tid] = B[tid];

    const int bx = blockIdx.x, by = blockIdx.y;
    const int ix0 = 2 * (bx * 16) - 1;
    const int iy0 = 2 * (by * 16) - 1;
    const int sx = tid & 7, sy = (tid >> 3) & 7, og = tid >> 6;

    float acc[4][4];
    #pragma unroll
    for (int o = 0; o < 4; o++)
        #pragma unroll
        for (int q = 0; q < 4; q++) acc[o][q] = 0.f;

    for (int ic0 = 0; ic0 < 32; ic0 += 8) {
        __syncthreads();
        for (int i = tid; i < 16 * 8 * 9; i += 256) {
            int oc = i / 72, rem = i % 72;
            int ic = rem / 9, t = rem % 9;
            s_w[i] = W[(oc * 32 + ic0 + ic) * 9 + t];
        }
        for (int i = tid; i < 8 * 33 * 33; i += 256) {
            int ic = i / (33 * 33);
            int rem = i % (33 * 33);
            int rr = rem / 33, col = rem % 33;
            int iy = iy0 + rr, ix = ix0 + col;
            float v = 0.f;
            if (iy >= 0 && iy < 256 && ix >= 0 && ix < 256)
                v = in[((size_t)(ic0 + ic) * 256 + iy) * 256 + ix];
            s_in[(ic * 33 + rr) * 34 + col] = v;
        }
        __syncthreads();
        #pragma unroll
        for (int ic = 0; ic < 8; ic++) {
            float inr[4][9];
            #pragma unroll
            for (int q = 0; q < 4; q++) {
                int rb = 2 * sy + (q >> 1) * 16;
                int cb = 2 * sx + (q & 1) * 16;
                #pragma unroll
                for (int ky = 0; ky < 3; ky++)
                    #pragma unroll
                    for (int kx = 0; kx < 3; kx++)
                        inr[q][ky * 3 + kx] = s_in[(ic * 33 + rb + ky) * 34 + cb + kx];
            }
            #pragma unroll
            for (int o = 0; o < 4; o++) {
                int oc = og * 4 + o;
                #pragma unroll
                for (int t = 0; t < 9; t++) {
                    float w = s_w[(oc * 8 + ic) * 9 + t];
                    acc[o][0] += w * inr[0][t];
                    acc[o][1] += w * inr[1][t];
                    acc[o][2] += w * inr[2][t];
                    acc[o][3] += w * inr[3][t];
                }
            }
        }
    }
    float* outb = &g_F3[net][0];
    const int oy0 = by * 16 + sy, ox0 = bx * 16 + sx;
    #pragma unroll
    for (int o = 0; o < 4; o++) {
        int oc = og * 4 + o;
        float bb = s_b[oc];
        #pragma unroll
        for (int q = 0; q < 4; q++) {
            int oy = oy0 + (q >> 1) * 8, ox = ox0 + (q & 1) * 8;
            outb[((size_t)oc * 128 + oy) * 128 + ox] = acc[o][q] + bb;
        }
    }
}

// =====================================================================
// pool: warp per p; lane-parallel gather + shfl max
// =====================================================================
__global__ void k_pool(const int* __restrict__ fgc, const int* __restrict__ fgs)
{
    const int net = blockIdx.y;
    const int* __restrict__ fg = net ? fgc : fgs;
    const int warp = threadIdx.x >> 5, lane = threadIdx.x & 31;
    const int p = blockIdx.x * 8 + warp;
    const int idx = fg[p * 32 + lane];
    const float* __restrict__ f = &g_F3[net][0];
    float m[16];
    #pragma unroll
    for (int c = 0; c < 16; c++) m[c] = f[c * 16384 + idx];
    #pragma unroll
    for (int c = 0; c < 16; c++) {
        float v = m[c];
        #pragma unroll
        for (int off = 16; off; off >>= 1) v = fmaxf(v, __shfl_xor_sync(0xffffffffu, v, off));
        if (lane == 0) g_POOL[net][c * 256 + p] = v;
    }
}

// =====================================================================
// fc: mat[net][o] = fc_b[o] + dot(pooled[net], fc_w[o, :])
// =====================================================================
__global__ void k_fc(const float* __restrict__ fcw0, const float* __restrict__ fcb0,
                     const float* __restrict__ fcw1, const float* __restrict__ fcb1)
{
    const int net = blockIdx.y;
    const float* __restrict__ Wm = net ? fcw1 : fcw0;
    const float* __restrict__ Bm = net ? fcb1 : fcb0;
    __shared__ __align__(16) float s_p[4096];
    const int tid = threadIdx.x;
    for (int i = tid; i < 4096; i += 256) s_p[i] = g_POOL[net][i];
    __syncthreads();
    const int warp = tid >> 5, lane = tid & 31;
    const int o = blockIdx.x * 8 + warp;
    const float4* __restrict__ row = (const float4*)(Wm + (size_t)o * 4096);
    float sum = 0.f;
    #pragma unroll 4
    for (int i = lane; i < 1024; i += 32) {
        float4 w4 = row[i];
        sum += w4.x * s_p[i * 4] + w4.y * s_p[i * 4 + 1] +
               w4.z * s_p[i * 4 + 2] + w4.w * s_p[i * 4 + 3];
    }
    #pragma unroll
    for (int off = 16; off; off >>= 1) sum += __shfl_xor_sync(0xffffffffu, sum, off);
    if (lane == 0) g_MAT[net][o] = sum + Bm[o];
}

// =====================================================================
// wtrans: g_CWT[c*64+o] = cw[o*512+c]  (one-time 128KB transpose)
// =====================================================================
__global__ void k_wtrans(const float* __restrict__ cw)
{
    int i = blockIdx.x * 256 + threadIdx.x;   // 0..32767
    int c = i >> 6, o = i & 63;
    g_CWT[i] = cw[o * 512 + c];
}

// =====================================================================
// compress: CC[o][hw] = cb[o] + sum_c cw[o,c] * cF[c][hw]
// f32x2 oc-paired + 4-stage cp.async pipeline with 16B transfers. (proven 34us)
// =====================================================================
__global__ void __launch_bounds__(256, 2) k_compress(
        const float* __restrict__ cF, const float* __restrict__ cb)
{
    __shared__ __align__(16) float s_in[4][16 * 64];   // 4 x 4 KB
    __shared__ __align__(16) float s_w[4][16 * 64];    // 4 x 4 KB, [c][o]
    const int tid = threadIdx.x;
    const int hw0 = blockIdx.x * 64;
    const int og = tid >> 5, hg = tid & 31;

    const int cI = tid >> 4, eI = (tid & 15) << 2;
    const size_t ibase = ((size_t)cI * 16384 + hw0 + eI) << 2;

    auto issue = [&](int c0, int buf) {
        unsigned di = (unsigned)__cvta_generic_to_shared(&s_in[buf][0]);
        unsigned dw = (unsigned)__cvta_generic_to_shared(&s_w[buf][0]);
        cpa16(di + 16u * tid, (const char*)cF + ibase + (size_t)c0 * 65536u);
        cpa16(dw + 16u * tid, (const char*)&g_CWT[c0 * 64] + 16u * tid);
    };

    u64t acc2[4][2];
    #pragma unroll
    for (int j = 0; j < 4; j++) { acc2[j][0] = 0ull; acc2[j][1] = 0ull; }

    issue(0, 0);  asm volatile("cp.async.commit_group;" ::: "memory");
    issue(16, 1); asm volatile("cp.async.commit_group;" ::: "memory");
    issue(32, 2); asm volatile("cp.async.commit_group;" ::: "memory");

    for (int k = 0; k < 32; k++) {
        asm volatile("cp.async.wait_group 2;" ::: "memory");
        __syncthreads();
        if (k + 3 < 32) issue((k + 3) * 16, (k + 3) & 3);
        asm volatile("cp.async.commit_group;" ::: "memory");

        const float* sin = s_in[k & 3];
        const float* sw  = s_w[k & 3];
        #pragma unroll
        for (int c = 0; c < 16; c++) {
            u64t b0 = pk2(sin[c * 64 + hg]);
            u64t b1 = pk2(sin[c * 64 + hg + 32]);
            const u64t* wp = (const u64t*)&sw[c * 64 + og * 8];
            u64t w2[4];
            #pragma unroll
            for (int j = 0; j < 4; j++) w2[j] = wp[j];
            #pragma unroll
            for (int j = 0; j < 4; j++) { fma2(acc2[j][0], w2[j], b0); fma2(acc2[j][1], w2[j], b1); }
        }
    }

    #pragma unroll
    for (int j = 0; j < 4; j++) {
        int oc0 = og * 8 + 2 * j;
        float bb0 = cb[oc0], bb1 = cb[oc0 + 1];
        float2 v0 = up2(acc2[j][0]);
        float2 v1 = up2(acc2[j][1]);
        g_CC[(size_t)oc0 * 16384 + hw0 + hg]            = v0.x + bb0;
        g_CC[(size_t)(oc0+1) * 16384 + hw0 + hg]        = v0.y + bb1;
        g_CC[(size_t)oc0 * 16384 + hw0 + hg + 32]       = v1.x + bb0;
        g_CC[(size_t)(oc0+1) * 16384 + hw0 + hg + 32]   = v1.y + bb1;
    }
}

// row means of CC
__global__ void k_mean()
{
    const int o = blockIdx.x;
    __shared__ float red[256];
    const int tid = threadIdx.x;
    float s = 0.f;
    const float4* __restrict__ row = (const float4*)&g_CC[(size_t)o * 16384];
    for (int i = tid; i < 4096; i += 256) {
        float4 v = row[i];
        s += v.x + v.y + v.z + v.w;
    }
    red[tid] = s;
    __syncthreads();
    for (int k = 128; k; k >>= 1) { if (tid < k) red[tid] += red[tid + k]; __syncthreads(); }
    if (tid == 0) g_MEAN[o] = red[0] * (1.f / 16384.f);
}

// TF = CC - mean
__global__ void k_tfinit()
{
    int idx = blockIdx.x * 256 + threadIdx.x;
    float m = g_MEAN[idx >> 12];
    float4 v = ((const float4*)g_CC)[idx];
    v.x -= m; v.y -= m; v.z -= m; v.w -= m;
    ((float4*)g_TF)[idx] = v;
}

// TFG = (sMat@cMat) @ (CC - mean)[:, fgc]; T computed in-block from g_MAT
__global__ void k_transfg(const int* __restrict__ fgc)
{
    __shared__ __align__(16) float s_g[64 * 128];
    __shared__ __align__(16) float s_T[64 * 64];
    const int tid = threadIdx.x;
    const int k0 = blockIdx.x * 128;
    for (int i = tid; i < 4096; i += 256) { s_g[i] = g_MAT[0][i]; s_g[4096 + i] = g_MAT[1][i]; }
    __syncthreads();
    for (int e = tid; e < 4096; e += 256) {
        int i = e >> 6, j = e & 63;
        float sum = 0.f;
        #pragma unroll 8
        for (int k = 0; k < 64; k++) sum += s_g[i * 64 + k] * s_g[4096 + k * 64 + j];
        s_T[e] = sum;
    }
    __syncthreads();
    for (int i = tid; i < 64 * 128; i += 256) {
        int m = i >> 7, j = i & 127;
        int col = fgc[k0 + j];
        s_g[i] = g_CC[(size_t)m * 16384 + col] - g_MEAN[m];
    }
    __syncthreads();
    const int og = tid >> 5, hg = tid & 31;
    float acc[8][4];
    #pragma unroll
    for (int o = 0; o < 8; o++)
        #pragma unroll
        for (int q = 0; q < 4; q++) acc[o][q] = 0.f;
    #pragma unroll 4
    for (int m = 0; m < 64; m++) {
        float in4[4];
        #pragma unroll
        for (int q = 0; q < 4; q++) in4[q] = s_g[m * 128 + hg + 32 * q];
        #pragma unroll
        for (int o = 0; o < 8; o++) {
            float w = s_T[(og * 8 + o) * 64 + m];
            #pragma unroll
            for (int q = 0; q < 4; q++) acc[o][q] += w * in4[q];
        }
    }
    #pragma unroll
    for (int o = 0; o < 8; o++)
        #pragma unroll
        for (int q = 0; q < 4; q++)
            g_TFG[(size_t)(og * 8 + o) * 8192 + k0 + hg + 32 * q] = acc[o][q];
}

// scatter TFG into TF at fg columns (duplicates write identical values)
__global__ void k_scatter(const int* __restrict__ fgc)
{
    int idx = blockIdx.x * 256 + threadIdx.x;
    int o = idx >> 13, k = idx & 8191;
    g_TF[(size_t)o * 16384 + fgc[k]] = g_TFG[idx];
}

// =====================================================================
// unzip: out[u][hw] = ub[u] + sum_o uw[u,o] * TF[o][hw]   (f32x2 u-paired)
// =====================================================================
__global__ void k_unzip(const float* __restrict__ uw, const float* __restrict__ ub,
                        float* __restrict__ out)
{
    __shared__ __align__(16) float s_tf[64 * 128];   // 32 KB
    __shared__ __align__(16) float s_w[64 * 64];     // [o][u], 16 KB
    const int tid = threadIdx.x;
    const int u0 = blockIdx.y * 64;
    const int hw0 = blockIdx.x * 128;
    for (int i = tid; i < 64 * 128; i += 256) {
        int o = i >> 7, hw = i & 127;
        s_tf[i] = g_TF[(size_t)o * 16384 + hw0 + hw];
    }
    for (int i = tid; i < 64 * 64; i += 256) {
        int o = i >> 6, u = i & 63;
        s_w[i] = uw[(size_t)(u0 + u) * 64 + o];
    }
    __syncthreads();
    const int ug = tid >> 5, hg = tid & 31;
    u64t acc2[4][4];
    #pragma unroll
    for (int j = 0; j < 4; j++)
        #pragma unroll
        for (int q = 0; q < 4; q++) acc2[j][q] = 0ull;
    #pragma unroll 4
    for (int o = 0; o < 64; o++) {
        u64t b2[4];
        #pragma unroll
        for (int q = 0; q < 4; q++) b2[q] = pk2(s_tf[o * 128 + hg + 32 * q]);
        const u64t* wp = (const u64t*)&s_w[o * 64 + ug * 8];
        u64t w2[4];
        #pragma unroll
        for (int j = 0; j < 4; j++) w2[j] = wp[j];
        #pragma unroll
        for (int j = 0; j < 4; j++)
            #pragma unroll
            for (int q = 0; q < 4; q++) fma2(acc2[j][q], w2[j], b2[q]);
    }
    #pragma unroll
    for (int j = 0; j < 4; j++) {
        int u = u0 + ug * 8 + 2 * j;
        float bb0 = ub[u], bb1 = ub[u + 1];
        #pragma unroll
        for (int q = 0; q < 4; q++) {
            float2 v = up2(acc2[j][q]);
            out[(size_t)u * 16384 + hw0 + hg + 32 * q]       = v.x + bb0;
            out[(size_t)(u+1) * 16384 + hw0 + hg + 32 * q]   = v.y + bb1;
        }
    }
}

// =====================================================================
extern "C" void kernel_launch(void* const* d_in, const int* in_sizes, int n_in,
                              void* d_out, int out_size)
{
    const float* cF      = (const float*)d_in[0];
    const float* content = (const float*)d_in[2];
    const float* style   = (const float*)d_in[3];
    const float* s_c1w = (const float*)d_in[4];
    const float* s_c1b = (const float*)d_in[5];
    const float* s_c2w = (const float*)d_in[6];
    const float* s_c2b = (const float*)d_in[7];
    const float* s_c3w = (const float*)d_in[8];
    const float* s_c3b = (const float*)d_in[9];
    const float* s_fcw = (const float*)d_in[10];
    const float* s_fcb = (const float*)d_in[11];
    const float* c_c1w = (const float*)d_in[12];
    const float* c_c1b = (const float*)d_in[13];
    const float* c_c2w = (const float*)d_in[14];
    const float* c_c2b = (const float*)d_in[15];
    const float* c_c3w = (const float*)d_in[16];
    const float* c_c3b = (const float*)d_in[17];
    const float* c_fcw = (const float*)d_in[18];
    const float* c_fcb = (const float*)d_in[19];
    const float* compress_w = (const float*)d_in[20];
    const float* compress_b = (const float*)d_in[21];
    const float* unzip_w = (const float*)d_in[22];
    const float* unzip_b = (const float*)d_in[23];
    const int* fgc = (const int*)d_in[24];
    const int* fgs = (const int*)d_in[25];
    float* out = (float*)d_out;

    // Fork: branch B (compress path) on side stream overlaps branch A (conv path).
    cudaEventRecord(g_evA, 0);
    cudaStreamWaitEvent(g_s2, g_evA, 0);

    // branch A (main stream)
    k_conv1<<<dim3(16, 32, 2), dim3(16, 16)>>>(style, content, s_c1w, s_c1b, c_c1w, c_c1b); // 1
    k_conv2<<<dim3(8, 16, 2), 256>>>(s_c2w, s_c2b, c_c2w, c_c2b);     // 2

    // branch B (side stream)
    k_wtrans<<<128, 256, 0, g_s2>>>(compress_w);                      // 3
    k_compress<<<256, 256, 0, g_s2>>>(cF, compress_b);                // 4 <-- profiled
    k_mean<<<64, 256, 0, g_s2>>>();                                   // 5
    k_tfinit<<<1024, 256, 0, g_s2>>>();                               // 6

    // branch A continues
    k_conv3<<<dim3(8, 8, 2), 256>>>(s_c3w, s_c3b, c_c3w, c_c3b);      // 7
    k_pool<<<dim3(32, 2), 256>>>(fgc, fgs);                           // 8
    k_fc<<<dim3(512, 2), 256>>>(s_fcw, s_fcb, c_fcw, c_fcb);          // 9

    // join: transfg needs both branches
    cudaEventRecord(g_evB, g_s2);
    cudaStreamWaitEvent(0, g_evB, 0);

    k_transfg<<<64, 256>>>(fgc);                                      // 10
    k_scatter<<<2048, 256>>>(fgc);                                    // 11
    k_unzip<<<dim3(128, 8), 256>>>(unzip_w, unzip_b, out);            // 12
}

// round 17
// speedup vs baseline: 1.4407x; 1.4407x over previous
#include <cuda_runtime.h>

// ---------------- f32x2 packed-FMA helpers ----------------
typedef unsigned long long u64t;
__device__ __forceinline__ u64t pk2(float v){ u64t r; asm("mov.b64 %0,{%1,%1};" : "=l"(r) : "f"(v)); return r; }
__device__ __forceinline__ void fma2(u64t& d, u64t a, u64t b){ asm("fma.rn.f32x2 %0,%1,%2,%0;" : "+l"(d) : "l"(a), "l"(b)); }
__device__ __forceinline__ float2 up2(u64t v){ float2 f; asm("mov.b64 {%0,%1},%2;" : "=f"(f.x), "=f"(f.y) : "l"(v)); return f; }

// cp.async 4B with zero-fill when sz==0
__device__ __forceinline__ void cpa4(unsigned dst, const void* src, int sz){
    asm volatile("cp.async.ca.shared.global [%0], [%1], 4, %2;" :: "r"(dst), "l"(src), "r"(sz));
}
// cp.async 16B (.cg form)
__device__ __forceinline__ void cpa16(unsigned dst, const void* src){
    asm volatile("cp.async.cg.shared.global [%0], [%1], 16;" :: "r"(dst), "l"(src));
}

// ---------------- scratch (device globals; no allocation allowed) ----------------
__device__ float g_F1[2][64u*512u*512u];   // conv1 out, both nets (134 MB)
__device__ float g_F2[2][32u*256u*256u];   // conv2 out
__device__ float g_F3[2][16u*128u*128u];   // conv3 out
__device__ float g_POOL[2][4096];          // pooled features (c*256+p)
__device__ float g_MAT[2][4096];           // sMat (net0), cMat (net1), row-major 64x64
__device__ float g_CC[64*16384];           // compress output
__device__ float g_MEAN[64];               // row means of CC
__device__ float g_TF[64*16384];           // ccf with fg columns replaced
__device__ float g_CWT[512*64];            // compress weights transposed [c][o]

// =====================================================================
// conv1: (3,1024,1024) -> (64,512,512), k=3 s=2 p=1, +bias, ReLU (scalar, proven)
// =====================================================================
__global__ void k_conv1(const float* __restrict__ img0, const float* __restrict__ img1,
                        const float* __restrict__ w0, const float* __restrict__ b0,
                        const float* __restrict__ w1, const float* __restrict__ b1)
{
    const int net = blockIdx.z;
    const float* __restrict__ img = net ? img1 : img0;
    const float* __restrict__ W   = net ? w1 : w0;
    const float* __restrict__ B   = net ? b1 : b0;

    __shared__ __align__(16) float s_w[64 * 28];
    __shared__ __align__(16) float s_in[3 * 33 * 65];
    __shared__ float s_b[64];

    const int tid = threadIdx.y * 16 + threadIdx.x;
    for (int i = tid; i < 64 * 28; i += 256) {
        int oc = i / 28, k = i - oc * 28;
        s_w[i] = (k < 27) ? W[oc * 27 + k] : 0.f;
    }
    if (tid < 64) s_b[tid] = B[tid];

    const int bx = blockIdx.x, by = blockIdx.y;
    const int ix0 = 2 * (bx * 32) - 1;
    const int iy0 = 2 * (by * 16) - 1;
    for (int i = tid; i < 3 * 33 * 65; i += 256) {
        int c = i / (33 * 65);
        int rem = i % (33 * 65);
        int r = rem / 65, col = rem % 65;
        int iy = iy0 + r, ix = ix0 + col;
        float v = 0.f;
        if (iy >= 0 && iy < 1024 && ix >= 0 && ix < 1024)
            v = img[(c * 1024 + iy) * 1024 + ix];
        s_in[i] = v;
    }
    __syncthreads();

    const int tx = threadIdx.x, ty = threadIdx.y;
    float r[54];
    #pragma unroll
    for (int c = 0; c < 3; c++)
        #pragma unroll
        for (int ky = 0; ky < 3; ky++) {
            int base = c * 33 * 65 + (2 * ty + ky) * 65 + 2 * tx;
            #pragma unroll
            for (int kx = 0; kx < 3; kx++) {
                r[(c * 3 + ky) * 6 + kx]     = s_in[base + kx];
                r[(c * 3 + ky) * 6 + 3 + kx] = s_in[base + 32 + kx];
            }
        }

    const int oy = by * 16 + ty;
    const int ox = bx * 32 + tx;
    float* outp = &g_F1[net][0] + (size_t)oy * 512 + ox;
    #pragma unroll 2
    for (int oc = 0; oc < 64; oc++) {
        float w[28];
        const float4* wr = (const float4*)&s_w[oc * 28];
        #pragma unroll
        for (int j = 0; j < 7; j++) {
            float4 t4 = wr[j];
            w[4*j] = t4.x; w[4*j+1] = t4.y; w[4*j+2] = t4.z; w[4*j+3] = t4.w;
        }
        float a0 = s_b[oc], a1 = s_b[oc];
        #pragma unroll
        for (int k = 0; k < 27; k++) {
            a0 += w[k] * r[(k / 3) * 6 + (k % 3)];
            a1 += w[k] * r[(k / 3) * 6 + 3 + (k % 3)];
        }
        outp[(size_t)oc * 262144]      = fmaxf(a0, 0.f);
        outp[(size_t)oc * 262144 + 16] = fmaxf(a1, 0.f);
    }
}

// =====================================================================
// conv2: f32x2 + 4-stage cp.async pipeline (proven, 135us)
// =====================================================================
__global__ void __launch_bounds__(256, 2) k_conv2(
        const float* __restrict__ w0, const float* __restrict__ b0,
        const float* __restrict__ w1, const float* __restrict__ b1)
{
    const int net = blockIdx.z;
    const float* __restrict__ W = net ? w1 : w0;   // (32,64,3,3)
    const float* __restrict__ B = net ? b1 : b0;
    const float* __restrict__ in = &g_F1[net][0];

    __shared__ __align__(16) float s_in[4][33 * 65];   // 4 x 2145
    __shared__ __align__(16) float s_w[4][9 * 32];     // 4 x 288, [t][oc]
    __shared__ float s_b[32];

    const int tid = threadIdx.x;
    if (tid < 32) s_b[tid] = B[tid];

    const int x0 = blockIdx.x * 32;
    const int y0 = blockIdx.y * 16;
    const int ix0 = 2 * x0 - 1;
    const int iy0 = 2 * y0 - 1;
    const int tx = tid & 15, og = (tid >> 4) & 3, ty = tid >> 6;

    int goff[9];
    #pragma unroll
    for (int j = 0; j < 9; j++) {
        int i = tid + j * 256;
        int rr = i / 65, col = i - rr * 65;
        int iy = iy0 + rr, ix = ix0 + col;
        bool ok = (i < 2145) && iy >= 0 && iy < 512 && ix >= 0 && ix < 512;
        goff[j] = ok ? (((iy * 512 + ix) << 2) | 1) : 0;
    }
    const int t0w = tid >> 5, oc0w = tid & 31;
    const int woff0 = (oc0w * 576 + t0w) << 2;
    const bool w1v = tid < 32;
    const int woff1 = (oc0w * 576 + 8) << 2;

    u64t acc2[4][8];
    #pragma unroll
    for (int j = 0; j < 4; j++)
        #pragma unroll
        for (int p = 0; p < 8; p++) acc2[j][p] = 0ull;

    auto issue = [&](int ic, int buf) {
        unsigned dw = (unsigned)__cvta_generic_to_shared(&s_w[buf][0]);
        const char* wB = (const char*)W + ic * 36;
        cpa4(dw + 4u * tid, wB + woff0, 4);
        if (w1v) cpa4(dw + 4u * (tid + 256), wB + woff1, 4);
        unsigned di = (unsigned)__cvta_generic_to_shared(&s_in[buf][0]);
        const char* iB = (const char*)in + (size_t)ic * 1048576u;
        #pragma unroll
        for (int j = 0; j < 8; j++) {
            int e = goff[j];
            cpa4(di + 4u * (tid + j * 256), iB + (e & ~3), (e & 1) << 2);
        }
        if (tid < 97) {
            int e = goff[8];
            cpa4(di + 4u * (tid + 2048), iB + (e & ~3), (e & 1) << 2);
        }
    };

    issue(0, 0); asm volatile("cp.async.commit_group;" ::: "memory");
    issue(1, 1); asm volatile("cp.async.commit_group;" ::: "memory");
    issue(2, 2); asm volatile("cp.async.commit_group;" ::: "memory");

    for (int k = 0; k < 64; k++) {
        asm volatile("cp.async.wait_group 2;" ::: "memory");
        __syncthreads();
        if (k + 3 < 64) issue(k + 3, (k + 3) & 3);
        asm volatile("cp.async.commit_group;" ::: "memory");

        const float* sp = s_in[k & 3];
        const float* sw = s_w[k & 3];
        #pragma unroll
        for (int t = 0; t < 9; t++) {
            const int ky = t / 3, kx = t - ky * 3;
            const u64t* wp = (const u64t*)&sw[t * 32 + og * 8];
            u64t w2[4];
            #pragma unroll
            for (int j = 0; j < 4; j++) w2[j] = wp[j];
            u64t b2[8];
            #pragma unroll
            for (int kk = 0; kk < 4; kk++) {
                int row = 2 * (ty + 4 * kk) + ky;
                b2[kk*2]   = pk2(sp[row * 65 + 2 * tx + kx]);
                b2[kk*2+1] = pk2(sp[row * 65 + 2 * tx + 32 + kx]);
            }
            #pragma unroll
            for (int j = 0; j < 4; j++)
                #pragma unroll
                for (int p = 0; p < 8; p++)
                    fma2(acc2[j][p], w2[j], b2[p]);
        }
    }

    float* outb = &g_F2[net][0];
    #pragma unroll
    for (int j = 0; j < 4; j++) {
        int oc0 = og * 8 + 2 * j;
        float bb0 = s_b[oc0], bb1 = s_b[oc0 + 1];
        #pragma unroll
        for (int k = 0; k < 4; k++) {
            int oy = y0 + ty + 4 * k;
            float2 vA = up2(acc2[j][k*2]);
            float2 vB = up2(acc2[j][k*2+1]);
            float* opA = &outb[((size_t)oc0 * 256 + oy) * 256 + x0 + tx];
            float* opB = &outb[((size_t)(oc0+1) * 256 + oy) * 256 + x0 + tx];
            opA[0]  = fmaxf(vA.x + bb0, 0.f);
            opB[0]  = fmaxf(vA.y + bb1, 0.f);
            opA[16] = fmaxf(vB.x + bb0, 0.f);
            opB[16] = fmaxf(vB.y + bb1, 0.f);
        }
    }
}

// =====================================================================
// conv3: (32,256,256) -> (16,128,128), +bias, NO relu (scalar, proven)
// =====================================================================
__global__ void k_conv3(const float* __restrict__ w0, const float* __restrict__ b0,
                        const float* __restrict__ w1, const float* __restrict__ b1)
{
    const int net = blockIdx.z;
    const float* __restrict__ W = net ? w1 : w0;   // (16,32,3,3)
    const float* __restrict__ B = net ? b1 : b0;
    const float* __restrict__ in = &g_F2[net][0];

    __shared__ __align__(16) float s_in[8 * 33 * 34];
    __shared__ __align__(16) float s_w[16 * 8 * 9];
    __shared__ float s_b[16];

    const int tid = threadIdx.x;
    if (tid < 16) s_b[tid] = B[tid];

    const int bx = blockIdx.x, by = blockIdx.y;
    const int ix0 = 2 * (bx * 16) - 1;
    const int iy0 = 2 * (by * 16) - 1;
    const int sx = tid & 7, sy = (tid >> 3) & 7, og = tid >> 6;

    float acc[4][4];
    #pragma unroll
    for (int o = 0; o < 4; o++)
        #pragma unroll
        for (int q = 0; q < 4; q++) acc[o][q] = 0.f;

    for (int ic0 = 0; ic0 < 32; ic0 += 8) {
        __syncthreads();
        for (int i = tid; i < 16 * 8 * 9; i += 256) {
            int oc = i / 72, rem = i % 72;
            int ic = rem / 9, t = rem % 9;
            s_w[i] = W[(oc * 32 + ic0 + ic) * 9 + t];
        }
        for (int i = tid; i < 8 * 33 * 33; i += 256) {
            int ic = i / (33 * 33);
            int rem = i % (33 * 33);
            int rr = rem / 33, col = rem % 33;
            int iy = iy0 + rr, ix = ix0 + col;
            float v = 0.f;
            if (iy >= 0 && iy < 256 && ix >= 0 && ix < 256)
                v = in[((size_t)(ic0 + ic) * 256 + iy) * 256 + ix];
            s_in[(ic * 33 + rr) * 34 + col] = v;
        }
        __syncthreads();
        #pragma unroll
        for (int ic = 0; ic < 8; ic++) {
            float inr[4][9];
            #pragma unroll
            for (int q = 0; q < 4; q++) {
                int rb = 2 * sy + (q >> 1) * 16;
                int cb = 2 * sx + (q & 1) * 16;
                #pragma unroll
                for (int ky = 0; ky < 3; ky++)
                    #pragma unroll
                    for (int kx = 0; kx < 3; kx++)
                        inr[q][ky * 3 + kx] = s_in[(ic * 33 + rb + ky) * 34 + cb + kx];
            }
            #pragma unroll
            for (int o = 0; o < 4; o++) {
                int oc = og * 4 + o;
                #pragma unroll
                for (int t = 0; t < 9; t++) {
                    float w = s_w[(oc * 8 + ic) * 9 + t];
                    acc[o][0] += w * inr[0][t];
                    acc[o][1] += w * inr[1][t];
                    acc[o][2] += w * inr[2][t];
                    acc[o][3] += w * inr[3][t];
                }
            }
        }
    }
    float* outb = &g_F3[net][0];
    const int oy0 = by * 16 + sy, ox0 = bx * 16 + sx;
    #pragma unroll
    for (int o = 0; o < 4; o++) {
        int oc = og * 4 + o;
        float bb = s_b[oc];
        #pragma unroll
        for (int q = 0; q < 4; q++) {
            int oy = oy0 + (q >> 1) * 8, ox = ox0 + (q & 1) * 8;
            outb[((size_t)oc * 128 + oy) * 128 + ox] = acc[o][q] + bb;
        }
    }
}

// =====================================================================
// pool: warp per p; lane-parallel gather + shfl max
// =====================================================================
__global__ void k_pool(const int* __restrict__ fgc, const int* __restrict__ fgs)
{
    const int net = blockIdx.y;
    const int* __restrict__ fg = net ? fgc : fgs;
    const int warp = threadIdx.x >> 5, lane = threadIdx.x & 31;
    const int p = blockIdx.x * 8 + warp;
    const int idx = fg[p * 32 + lane];
    const float* __restrict__ f = &g_F3[net][0];
    float m[16];
    #pragma unroll
    for (int c = 0; c < 16; c++) m[c] = f[c * 16384 + idx];
    #pragma unroll
    for (int c = 0; c < 16; c++) {
        float v = m[c];
        #pragma unroll
        for (int off = 16; off; off >>= 1) v = fmaxf(v, __shfl_xor_sync(0xffffffffu, v, off));
        if (lane == 0) g_POOL[net][c * 256 + p] = v;
    }
}

// =====================================================================
// fc: mat[net][o] = fc_b[o] + dot(pooled[net], fc_w[o, :])  (unroll 8)
// =====================================================================
__global__ void k_fc(const float* __restrict__ fcw0, const float* __restrict__ fcb0,
                     const float* __restrict__ fcw1, const float* __restrict__ fcb1)
{
    const int net = blockIdx.y;
    const float* __restrict__ Wm = net ? fcw1 : fcw0;
    const float* __restrict__ Bm = net ? fcb1 : fcb0;
    __shared__ __align__(16) float s_p[4096];
    const int tid = threadIdx.x;
    for (int i = tid; i < 4096; i += 256) s_p[i] = g_POOL[net][i];
    __syncthreads();
    const int warp = tid >> 5, lane = tid & 31;
    const int o = blockIdx.x * 8 + warp;
    const float4* __restrict__ row = (const float4*)(Wm + (size_t)o * 4096);
    float sum = 0.f;
    #pragma unroll 8
    for (int i = lane; i < 1024; i += 32) {
        float4 w4 = row[i];
        sum += w4.x * s_p[i * 4] + w4.y * s_p[i * 4 + 1] +
               w4.z * s_p[i * 4 + 2] + w4.w * s_p[i * 4 + 3];
    }
    #pragma unroll
    for (int off = 16; off; off >>= 1) sum += __shfl_xor_sync(0xffffffffu, sum, off);
    if (lane == 0) g_MAT[net][o] = sum + Bm[o];
}

// =====================================================================
// wtrans: g_CWT[c*64+o] = cw[o*512+c]  (one-time 128KB transpose)
// =====================================================================
__global__ void k_wtrans(const float* __restrict__ cw)
{
    int i = blockIdx.x * 256 + threadIdx.x;   // 0..32767
    int c = i >> 6, o = i & 63;
    g_CWT[i] = cw[o * 512 + c];
}

// =====================================================================
// compress: f32x2 + 4-stage cp.async pipeline, 16B transfers (proven 34us)
// =====================================================================
__global__ void __launch_bounds__(256, 2) k_compress(
        const float* __restrict__ cF, const float* __restrict__ cb)
{
    __shared__ __align__(16) float s_in[4][16 * 64];   // 4 x 4 KB
    __shared__ __align__(16) float s_w[4][16 * 64];    // 4 x 4 KB, [c][o]
    const int tid = threadIdx.x;
    const int hw0 = blockIdx.x * 64;
    const int og = tid >> 5, hg = tid & 31;

    const int cI = tid >> 4, eI = (tid & 15) << 2;
    const size_t ibase = ((size_t)cI * 16384 + hw0 + eI) << 2;

    auto issue = [&](int c0, int buf) {
        unsigned di = (unsigned)__cvta_generic_to_shared(&s_in[buf][0]);
        unsigned dw = (unsigned)__cvta_generic_to_shared(&s_w[buf][0]);
        cpa16(di + 16u * tid, (const char*)cF + ibase + (size_t)c0 * 65536u);
        cpa16(dw + 16u * tid, (const char*)&g_CWT[c0 * 64] + 16u * tid);
    };

    u64t acc2[4][2];
    #pragma unroll
    for (int j = 0; j < 4; j++) { acc2[j][0] = 0ull; acc2[j][1] = 0ull; }

    issue(0, 0);  asm volatile("cp.async.commit_group;" ::: "memory");
    issue(16, 1); asm volatile("cp.async.commit_group;" ::: "memory");
    issue(32, 2); asm volatile("cp.async.commit_group;" ::: "memory");

    for (int k = 0; k < 32; k++) {
        asm volatile("cp.async.wait_group 2;" ::: "memory");
        __syncthreads();
        if (k + 3 < 32) issue((k + 3) * 16, (k + 3) & 3);
        asm volatile("cp.async.commit_group;" ::: "memory");

        const float* sin = s_in[k & 3];
        const float* sw  = s_w[k & 3];
        #pragma unroll
        for (int c = 0; c < 16; c++) {
            u64t b0 = pk2(sin[c * 64 + hg]);
            u64t b1 = pk2(sin[c * 64 + hg + 32]);
            const u64t* wp = (const u64t*)&sw[c * 64 + og * 8];
            u64t w2[4];
            #pragma unroll
            for (int j = 0; j < 4; j++) w2[j] = wp[j];
            #pragma unroll
            for (int j = 0; j < 4; j++) { fma2(acc2[j][0], w2[j], b0); fma2(acc2[j][1], w2[j], b1); }
        }
    }

    #pragma unroll
    for (int j = 0; j < 4; j++) {
        int oc0 = og * 8 + 2 * j;
        float bb0 = cb[oc0], bb1 = cb[oc0 + 1];
        float2 v0 = up2(acc2[j][0]);
        float2 v1 = up2(acc2[j][1]);
        g_CC[(size_t)oc0 * 16384 + hw0 + hg]            = v0.x + bb0;
        g_CC[(size_t)(oc0+1) * 16384 + hw0 + hg]        = v0.y + bb1;
        g_CC[(size_t)oc0 * 16384 + hw0 + hg + 32]       = v1.x + bb0;
        g_CC[(size_t)(oc0+1) * 16384 + hw0 + hg + 32]   = v1.y + bb1;
    }
}

// row means of CC
__global__ void k_mean()
{
    const int o = blockIdx.x;
    __shared__ float red[256];
    const int tid = threadIdx.x;
    float s = 0.f;
    const float4* __restrict__ row = (const float4*)&g_CC[(size_t)o * 16384];
    for (int i = tid; i < 4096; i += 256) {
        float4 v = row[i];
        s += v.x + v.y + v.z + v.w;
    }
    red[tid] = s;
    __syncthreads();
    for (int k = 128; k; k >>= 1) { if (tid < k) red[tid] += red[tid + k]; __syncthreads(); }
    if (tid == 0) g_MEAN[o] = red[0] * (1.f / 16384.f);
}

// TF = CC - mean
__global__ void k_tfinit()
{
    int idx = blockIdx.x * 256 + threadIdx.x;
    float m = g_MEAN[idx >> 12];
    float4 v = ((const float4*)g_CC)[idx];
    v.x -= m; v.y -= m; v.z -= m; v.w -= m;
    ((float4*)g_TF)[idx] = v;
}

// TFG = (sMat@cMat) @ (CC - mean)[:, fgc]; scatter fused: writes g_TF[:,fgc] directly.
// Duplicate fgc entries gather identical columns -> identical values -> benign race.
__global__ void k_transfg(const int* __restrict__ fgc)
{
    __shared__ __align__(16) float s_g[64 * 128];
    __shared__ __align__(16) float s_T[64 * 64];
    const int tid = threadIdx.x;
    const int k0 = blockIdx.x * 128;
    for (int i = tid; i < 4096; i += 256) { s_g[i] = g_MAT[0][i]; s_g[4096 + i] = g_MAT[1][i]; }
    __syncthreads();
    for (int e = tid; e < 4096; e += 256) {
        int i = e >> 6, j = e & 63;
        float sum = 0.f;
        #pragma unroll 8
        for (int k = 0; k < 64; k++) sum += s_g[i * 64 + k] * s_g[4096 + k * 64 + j];
        s_T[e] = sum;
    }
    __syncthreads();
    for (int i = tid; i < 64 * 128; i += 256) {
        int m = i >> 7, j = i & 127;
        int col = fgc[k0 + j];
        s_g[i] = g_CC[(size_t)m * 16384 + col] - g_MEAN[m];
    }
    __syncthreads();
    const int og = tid >> 5, hg = tid & 31;
    float acc[8][4];
    #pragma unroll
    for (int o = 0; o < 8; o++)
        #pragma unroll
        for (int q = 0; q < 4; q++) acc[o][q] = 0.f;
    #pragma unroll 4
    for (int m = 0; m < 64; m++) {
        float in4[4];
        #pragma unroll
        for (int q = 0; q < 4; q++) in4[q] = s_g[m * 128 + hg + 32 * q];
        #pragma unroll
        for (int o = 0; o < 8; o++) {
            float w = s_T[(og * 8 + o) * 64 + m];
            #pragma unroll
            for (int q = 0; q < 4; q++) acc[o][q] += w * in4[q];
        }
    }
    int col[4];
    #pragma unroll
    for (int q = 0; q < 4; q++) col[q] = fgc[k0 + hg + 32 * q];
    #pragma unroll
    for (int o = 0; o < 8; o++)
        #pragma unroll
        for (int q = 0; q < 4; q++)
            g_TF[(size_t)(og * 8 + o) * 16384 + col[q]] = acc[o][q];
}

// =====================================================================
// unzip: out[u][hw] = ub[u] + sum_o uw[u,o] * TF[o][hw]   (f32x2 u-paired)
// =====================================================================
__global__ void k_unzip(const float* __restrict__ uw, const float* __restrict__ ub,
                        float* __restrict__ out)
{
    __shared__ __align__(16) float s_tf[64 * 128];   // 32 KB
    __shared__ __align__(16) float s_w[64 * 64];     // [o][u], 16 KB
    const int tid = threadIdx.x;
    const int u0 = blockIdx.y * 64;
    const int hw0 = blockIdx.x * 128;
    for (int i = tid; i < 64 * 128; i += 256) {
        int o = i >> 7, hw = i & 127;
        s_tf[i] = g_TF[(size_t)o * 16384 + hw0 + hw];
    }
    for (int i = tid; i < 64 * 64; i += 256) {
        int o = i >> 6, u = i & 63;
        s_w[i] = uw[(size_t)(u0 + u) * 64 + o];
    }
    __syncthreads();
    const int ug = tid >> 5, hg = tid & 31;
    u64t acc2[4][4];
    #pragma unroll
    for (int j = 0; j < 4; j++)
        #pragma unroll
        for (int q = 0; q < 4; q++) acc2[j][q] = 0ull;
    #pragma unroll 4
    for (int o = 0; o < 64; o++) {
        u64t b2[4];
        #pragma unroll
        for (int q = 0; q < 4; q++) b2[q] = pk2(s_tf[o * 128 + hg + 32 * q]);
        const u64t* wp = (const u64t*)&s_w[o * 64 + ug * 8];
        u64t w2[4];
        #pragma unroll
        for (int j = 0; j < 4; j++) w2[j] = wp[j];
        #pragma unroll
        for (int j = 0; j < 4; j++)
            #pragma unroll
            for (int q = 0; q < 4; q++) fma2(acc2[j][q], w2[j], b2[q]);
    }
    #pragma unroll
    for (int j = 0; j < 4; j++) {
        int u = u0 + ug * 8 + 2 * j;
        float bb0 = ub[u], bb1 = ub[u + 1];
        #pragma unroll
        for (int q = 0; q < 4; q++) {
            float2 v = up2(acc2[j][q]);
            out[(size_t)u * 16384 + hw0 + hg + 32 * q]       = v.x + bb0;
            out[(size_t)(u+1) * 16384 + hw0 + hg + 32 * q]   = v.y + bb1;
        }
    }
}

// =====================================================================
extern "C" void kernel_launch(void* const* d_in, const int* in_sizes, int n_in,
                              void* d_out, int out_size)
{
    const float* cF      = (const float*)d_in[0];
    const float* content = (const float*)d_in[2];
    const float* style   = (const float*)d_in[3];
    const float* s_c1w = (const float*)d_in[4];
    const float* s_c1b = (const float*)d_in[5];
    const float* s_c2w = (const float*)d_in[6];
    const float* s_c2b = (const float*)d_in[7];
    const float* s_c3w = (const float*)d_in[8];
    const float* s_c3b = (const float*)d_in[9];
    const float* s_fcw = (const float*)d_in[10];
    const float* s_fcb = (const float*)d_in[11];
    const float* c_c1w = (const float*)d_in[12];
    const float* c_c1b = (const float*)d_in[13];
    const float* c_c2w = (const float*)d_in[14];
    const float* c_c2b = (const float*)d_in[15];
    const float* c_c3w = (const float*)d_in[16];
    const float* c_c3b = (const float*)d_in[17];
    const float* c_fcw = (const float*)d_in[18];
    const float* c_fcb = (const float*)d_in[19];
    const float* compress_w = (const float*)d_in[20];
    const float* compress_b = (const float*)d_in[21];
    const float* unzip_w = (const float*)d_in[22];
    const float* unzip_b = (const float*)d_in[23];
    const int* fgc = (const int*)d_in[24];
    const int* fgs = (const int*)d_in[25];
    float* out = (float*)d_out;

    // single stream (R15 proven); slot #4 profiled = k_conv3
    k_conv1<<<dim3(16, 32, 2), dim3(16, 16)>>>(style, content, s_c1w, s_c1b, c_c1w, c_c1b); // 1
    k_conv2<<<dim3(8, 16, 2), 256>>>(s_c2w, s_c2b, c_c2w, c_c2b);  // 2
    k_wtrans<<<128, 256>>>(compress_w);                            // 3
    k_conv3<<<dim3(8, 8, 2), 256>>>(s_c3w, s_c3b, c_c3w, c_c3b);   // 4 <-- profiled
    k_compress<<<256, 256>>>(cF, compress_b);                      // 5
    k_mean<<<64, 256>>>();                                         // 6
    k_tfinit<<<1024, 256>>>();                                     // 7
    k_pool<<<dim3(32, 2), 256>>>(fgc, fgs);                        // 8
    k_fc<<<dim3(512, 2), 256>>>(s_fcw, s_fcb, c_fcw, c_fcb);       // 9
    k_transfg<<<64, 256>>>(fgc);                                   // 10
    k_unzip<<<dim3(128, 8), 256>>>(unzip_w, unzip_b, out);         // 11
}